// round 11
// baseline (speedup 1.0000x reference)
#include <cuda_runtime.h>

// HolographicFMLayer: out[b,p,n] = sum_k X[b,i_p,k] * X[b,j_p,(n-k) mod 64]
// 276 pairs (i<j) over 24 fields, batch 2048, dim 64. Exact fp32 direct conv.
//
// R5-R11: LDS-wavefront-optimized. R4 measured L1=83.5% (binding) vs fma=53.4%:
// the 2 LDS.128 per 16 FFMA saturate the smem crossbar. Fix: pairs grouped by
// shared j so the per-lane window load serves TWO accumulator chains (i1,i2),
// and the two warp-halves split the k-sum (k<32 / k>=32) so 16 lanes cover all
// 64 outputs. 3 LDS.128 now feed 32 FFMA -> LDS/FMA halved. Cross-half
// reduction via 8x shfl_xor(16).

#define NF      24
#define NPAIR   276
#define DSTRIDE 132    // padded row stride (floats), 16B-aligned
#define NGROUP  144    // sum_j ceil(j/2), j=1..23; == 18 * 8 warps exactly

__global__ __launch_bounds__(256, 4)
void holo_conv_kernel(const float* __restrict__ in, float* __restrict__ out) {
    __shared__ __align__(16) float D[NF][DSTRIDE];
    __shared__ int G[NGROUP];

    const int b = blockIdx.x;
    const float* __restrict__ Xb = in + (size_t)b * (NF * 64);

    // Duplicated circular copies: D[f][m] = X[b][f][m mod 64], m in [0,128)
    for (int idx = threadIdx.x; idx < NF * 128; idx += 256) {
        int f = idx >> 7;
        int m = idx & 127;
        D[f][m] = Xb[(f << 6) + (m & 63)];
    }

    // Group table: for each j, pairs (i,j) packed two at a time.
    // Entry: i1 | i2<<5 | j<<10 | valid2<<15.
    if (threadIdx.x < NGROUP) {
        int g = threadIdx.x;
        int accu = 0, jj = 1, cc = 0;
        #pragma unroll 1
        for (int j = 1; j < NF; j++) {
            int nc = (j + 1) >> 1;
            if (g < accu + nc) { jj = j; cc = g - accu; break; }
            accu += nc;
        }
        int i1 = 2 * cc;
        int i2 = 2 * cc + 1;
        int v2 = (i2 < jj) ? 1 : 0;
        if (!v2) i2 = i1;  // duplicate; store predicated off
        G[g] = i1 | (i2 << 5) | (jj << 10) | (v2 << 15);
    }
    __syncthreads();

    const int warp = threadIdx.x >> 5;
    const int lane = threadIdx.x & 31;
    const int half = lane >> 4;     // k-range owner: 0 -> k<32, 1 -> k>=32
    const int s    = lane & 15;     // output sub-index
    const int n0   = s << 2;        // 4 outputs starting at n0
    const int t0   = half << 3;     // first t of this half's 8 steps

    for (int g = warp; g < NGROUP; g += 8) {
        const int e  = G[g];
        const int i1 = e & 31;
        const int i2 = (e >> 5) & 31;
        const int j  = (e >> 10) & 31;
        const int v2 = (e >> 15) & 1;

        const float* __restrict__ A1 = &D[i1][0];
        const float* __restrict__ A2 = &D[i2][0];
        const float* __restrict__ Dj = &D[j][0];

        float4 acc1 = make_float4(0.f, 0.f, 0.f, 0.f);
        float4 acc2 = make_float4(0.f, 0.f, 0.f, 0.f);

        // Sliding window of D[j]; Qb = D[j][64+n0-4t ..+3], Qa = D[j][60+n0-4t ..+3]
        float4 Qb = *reinterpret_cast<const float4*>(Dj + 64 + n0 - 4 * t0);

        #pragma unroll
        for (int t = 0; t < 8; t++) {
            const int tt = t0 + t;
            const float4 a1 = *reinterpret_cast<const float4*>(A1 + 64 + 4 * tt);
            const float4 a2 = *reinterpret_cast<const float4*>(A2 + 64 + 4 * tt);
            const float4 Qa = *reinterpret_cast<const float4*>(Dj + 60 + n0 - 4 * tt);

            // k = 4tt  : window aligned -> Qb
            acc1.x = fmaf(a1.x, Qb.x, acc1.x);  acc2.x = fmaf(a2.x, Qb.x, acc2.x);
            acc1.y = fmaf(a1.x, Qb.y, acc1.y);  acc2.y = fmaf(a2.x, Qb.y, acc2.y);
            acc1.z = fmaf(a1.x, Qb.z, acc1.z);  acc2.z = fmaf(a2.x, Qb.z, acc2.z);
            acc1.w = fmaf(a1.x, Qb.w, acc1.w);  acc2.w = fmaf(a2.x, Qb.w, acc2.w);
            // k = 4tt+1
            acc1.x = fmaf(a1.y, Qa.w, acc1.x);  acc2.x = fmaf(a2.y, Qa.w, acc2.x);
            acc1.y = fmaf(a1.y, Qb.x, acc1.y);  acc2.y = fmaf(a2.y, Qb.x, acc2.y);
            acc1.z = fmaf(a1.y, Qb.y, acc1.z);  acc2.z = fmaf(a2.y, Qb.y, acc2.z);
            acc1.w = fmaf(a1.y, Qb.z, acc1.w);  acc2.w = fmaf(a2.y, Qb.z, acc2.w);
            // k = 4tt+2
            acc1.x = fmaf(a1.z, Qa.z, acc1.x);  acc2.x = fmaf(a2.z, Qa.z, acc2.x);
            acc1.y = fmaf(a1.z, Qa.w, acc1.y);  acc2.y = fmaf(a2.z, Qa.w, acc2.y);
            acc1.z = fmaf(a1.z, Qb.x, acc1.z);  acc2.z = fmaf(a2.z, Qb.x, acc2.z);
            acc1.w = fmaf(a1.z, Qb.y, acc1.w);  acc2.w = fmaf(a2.z, Qb.y, acc2.w);
            // k = 4tt+3
            acc1.x = fmaf(a1.w, Qa.y, acc1.x);  acc2.x = fmaf(a2.w, Qa.y, acc2.x);
            acc1.y = fmaf(a1.w, Qa.z, acc1.y);  acc2.y = fmaf(a2.w, Qa.z, acc2.y);
            acc1.z = fmaf(a1.w, Qa.w, acc1.z);  acc2.z = fmaf(a2.w, Qa.w, acc2.z);
            acc1.w = fmaf(a1.w, Qb.x, acc1.w);  acc2.w = fmaf(a2.w, Qb.x, acc2.w);

            Qb = Qa;  // slide window (renamed away by full unroll)
        }

        // Cross-half k-reduction: lane and lane^16 hold the two k-halves.
        acc1.x += __shfl_xor_sync(0xFFFFFFFFu, acc1.x, 16);
        acc1.y += __shfl_xor_sync(0xFFFFFFFFu, acc1.y, 16);
        acc1.z += __shfl_xor_sync(0xFFFFFFFFu, acc1.z, 16);
        acc1.w += __shfl_xor_sync(0xFFFFFFFFu, acc1.w, 16);
        acc2.x += __shfl_xor_sync(0xFFFFFFFFu, acc2.x, 16);
        acc2.y += __shfl_xor_sync(0xFFFFFFFFu, acc2.y, 16);
        acc2.z += __shfl_xor_sync(0xFFFFFFFFu, acc2.z, 16);
        acc2.w += __shfl_xor_sync(0xFFFFFFFFu, acc2.w, 16);

        // half0 lanes store pair (i1,j); half1 lanes store pair (i2,j).
        if (half == 0) {
            const int p = ((i1 * (47 - i1)) >> 1) + j - i1 - 1;
            *reinterpret_cast<float4*>(out + ((size_t)b * NPAIR + p) * 64 + n0) = acc1;
        } else if (v2) {
            const int p = ((i2 * (47 - i2)) >> 1) + j - i2 - 1;
            *reinterpret_cast<float4*>(out + ((size_t)b * NPAIR + p) * 64 + n0) = acc2;
        }
    }
}

extern "C" void kernel_launch(void* const* d_in, const int* in_sizes, int n_in,
                              void* d_out, int out_size) {
    const float* in = (const float*)d_in[0];
    float* out = (float*)d_out;
    (void)in_sizes; (void)n_in; (void)out_size;
    holo_conv_kernel<<<2048, 256>>>(in, out);
}